// round 7
// baseline (speedup 1.0000x reference)
#include <cuda_runtime.h>
#include <cstdint>

// SNNModel: 3-layer LIF SNN, T=10. B=1024, D=4000, H=2048, O=1000.
// INT8 tensor-core path: mma.sync.m16n8k32.s8.s8.s32 (exact s32 accumulation).
// Weights decomposed into exact signed base-256 digits (24 bits): W*2^e = d0 + d1*2^-8 + d2*2^-16.
// Binary spikes exact in s8. Segment-weighted s32->fp32 folds at chunk boundaries.
// L1: x (3 digits) x W1 (3 digits), pairs with i+j<=3, grouped by weight class.

namespace {
constexpr int kB = 1024, kD = 4000, kH = 2048, kO = 1000, kT = 10;
constexpr int kL1Step = 3584;           // per-step K' bytes for layer 1 (28 chunks)
constexpr int kLd1 = kT * kL1Step;      // 35840
constexpr int kK2 = 3 * kH;             // 6144 bytes (3 digits x 2048)
constexpr int kOp = 1024;
}

// ---------------- persistent device buffers ----------------
__device__ __align__(16) float g_v1[kB * kH];
__device__ __align__(16) float g_v2[kB * kH];
__device__ __align__(16) float g_v3[kB * kO];
__device__ __align__(16) float g_acc1[kB * kH];
__device__ __align__(16) int8_t g_s1[kB * kH];
__device__ __align__(16) int8_t g_s2[kB * kH];
__device__ __align__(16) int8_t g_A1c[(size_t)kB * kLd1];
__device__ __align__(16) int8_t g_W1c[(size_t)kH * kLd1];
__device__ __align__(16) int8_t g_W2c[(size_t)kH * kK2];
__device__ __align__(16) int8_t g_W3c[(size_t)kOp * kK2];
__device__ unsigned g_maxbits[4];    // max |x|, |W1|, |W2|, |W3| as float bits
__device__ float g_sc[4];            // 2^e scale per matrix
__device__ float g_desc[3];          // descale per layer

// ---------------- PTX helpers ----------------
__device__ __forceinline__ uint32_t smem_u32(const void* p) {
    uint32_t a;
    asm("{ .reg .u64 t; cvta.to.shared.u64 t, %1; cvt.u32.u64 %0, t; }" : "=r"(a) : "l"(p));
    return a;
}
__device__ __forceinline__ void cp16(uint32_t dst, const void* src) {
    asm volatile("cp.async.cg.shared.global [%0], [%1], 16;" :: "r"(dst), "l"(src));
}
__device__ __forceinline__ void cp_commit() { asm volatile("cp.async.commit_group;" ::: "memory"); }
__device__ __forceinline__ void cp_wait1()  { asm volatile("cp.async.wait_group 1;" ::: "memory"); }
__device__ __forceinline__ void cp_wait0()  { asm volatile("cp.async.wait_group 0;" ::: "memory"); }
__device__ __forceinline__ void ldmx4(uint32_t& r0, uint32_t& r1, uint32_t& r2, uint32_t& r3,
                                      uint32_t addr) {
    asm volatile("ldmatrix.sync.aligned.m8n8.x4.shared.b16 {%0,%1,%2,%3}, [%4];"
                 : "=r"(r0), "=r"(r1), "=r"(r2), "=r"(r3) : "r"(addr));
}
__device__ __forceinline__ void mma_s8(int& c0, int& c1, int& c2, int& c3,
                                       uint32_t a0, uint32_t a1, uint32_t a2, uint32_t a3,
                                       uint32_t b0, uint32_t b1) {
    asm volatile(
        "mma.sync.aligned.m16n8k32.row.col.s32.s8.s8.s32 "
        "{%0,%1,%2,%3}, {%4,%5,%6,%7}, {%8,%9}, {%0,%1,%2,%3};"
        : "+r"(c0), "+r"(c1), "+r"(c2), "+r"(c3)
        : "r"(a0), "r"(a1), "r"(a2), "r"(a3), "r"(b0), "r"(b1));
}
__device__ __forceinline__ uint32_t sw128(uint32_t off) {
    return off ^ ((off >> 3) & 0x70);
}

// exact signed base-256 digit decomposition of v*sc (|v*sc| <= 127) to 24 bits
__device__ __forceinline__ void digits3(float v, float sc, int& d0, int& d1, int& d2) {
    float sv = v * sc;
    int I = __float2int_rn(sv * 65536.0f);
    d2 = ((I + 128) & 255) - 128; I = (I - d2) >> 8;
    d1 = ((I + 128) & 255) - 128; d0 = (I - d1) >> 8;
}

// L1 A-side layout map: j in [0,3584) -> x-digit index and kk, or pad (-1)
__device__ __forceinline__ int mapL1_A(int j, int& kk) {
    if (j < 400)  { kk = j;        return 0; }
    if (j < 512)  return -1;
    if (j < 912)  { kk = j - 512;  return 0; }
    if (j < 1312) { kk = j - 912;  return 1; }
    if (j < 1408) return -1;
    if (j < 1808) { kk = j - 1408; return 1; }
    if (j < 2208) { kk = j - 1808; return 0; }
    if (j < 2608) { kk = j - 2208; return 2; }
    if (j < 2688) return -1;
    if (j < 3088) { kk = j - 2688; return 1; }
    if (j < 3488) { kk = j - 3088; return 2; }
    return -1;
}

// ---------------- init / reduction / precompute kernels ----------------
__global__ void init_state() {
    int stride = gridDim.x * blockDim.x;
    int i0 = blockIdx.x * blockDim.x + threadIdx.x;
    for (int i = i0; i < kB * kH; i += stride) {
        g_v1[i] = 0.0f; g_v2[i] = 0.0f; g_acc1[i] = 0.0f;
    }
    for (int i = i0; i < kB * kO; i += stride) g_v3[i] = 0.0f;
    if (i0 < 4) g_maxbits[i0] = 0u;
}

__global__ void maxabs(const float* __restrict__ p, int n, int slot) {
    float m = 0.0f;
    int stride = gridDim.x * blockDim.x;
    for (int i = blockIdx.x * blockDim.x + threadIdx.x; i < n; i += stride)
        m = fmaxf(m, fabsf(p[i]));
#pragma unroll
    for (int off = 16; off >= 1; off >>= 1)
        m = fmaxf(m, __shfl_xor_sync(0xFFFFFFFFu, m, off));
    if ((threadIdx.x & 31) == 0)
        atomicMax(&g_maxbits[slot], __float_as_uint(m));
}

__global__ void calc_scales() {
    if (threadIdx.x != 0 || blockIdx.x != 0) return;
    int e[4];
    for (int i = 0; i < 4; i++) {
        float mx = __uint_as_float(g_maxbits[i]);
        int ei = 0;
        if (mx > 0.0f) {
            ei = ilogbf(127.0f / mx);
            while (ldexpf(mx, ei) > 127.0f) ei--;
            while (ldexpf(mx, ei + 1) <= 127.0f) ei++;
        }
        e[i] = ei;
        g_sc[i] = ldexpf(1.0f, ei);
    }
    g_desc[0] = ldexpf(1.0f, -(e[0] + e[1]));
    g_desc[1] = ldexpf(1.0f, -e[2]);
    g_desc[2] = ldexpf(1.0f, -e[3]);
}

// A1c[m, t*3584 + j] = x-digit per mapL1_A of x[m, t*400+kk], else 0
__global__ void build_xcat(const float* __restrict__ x) {
    long idx = (long)blockIdx.x * blockDim.x + threadIdx.x;
    if (idx >= (long)kB * kLd1) return;
    int m = (int)(idx / kLd1), c = (int)(idx % kLd1);
    int t = c / kL1Step, j = c % kL1Step;
    int kk, xd = mapL1_A(j, kk);
    int8_t o = 0;
    if (xd >= 0) {
        float xv = x[(long)m * kD + t * 400 + kk];
        int d0, d1, d2;
        digits3(xv, g_sc[0], d0, d1, d2);
        o = (int8_t)(xd == 0 ? d0 : xd == 1 ? d1 : d2);
    }
    g_A1c[idx] = o;
}

// W1c: digit layout matching A pairs per weight class
__global__ void build_w1(const float* __restrict__ W) {   // W: [4000, 2048]
    __shared__ float tile[32][33];
    int k0 = blockIdx.x * 32, n0 = blockIdx.y * 32;
    int tx = threadIdx.x & 31, ty = threadIdx.x >> 5;
    for (int i = 0; i < 32; i += 8)
        tile[ty + i][tx] = W[(long)(k0 + ty + i) * kH + n0 + tx];
    __syncthreads();
    float sc = g_sc[1];
    for (int i = 0; i < 32; i += 8) {
        int n = n0 + ty + i, kg = k0 + tx;
        int t = kg / 400, kk = kg % 400;
        int d0, d1, d2;
        digits3(tile[tx][ty + i], sc, d0, d1, d2);
        long base = (long)n * kLd1 + (long)t * kL1Step;
        g_W1c[base + kk]        = (int8_t)d0;   // class0 (0,0) -> w0
        g_W1c[base + 512 + kk]  = (int8_t)d1;   // class1 (0,1) -> w1
        g_W1c[base + 912 + kk]  = (int8_t)d0;   // class1 (1,0) -> w0
        g_W1c[base + 1408 + kk] = (int8_t)d1;   // class2 (1,1) -> w1
        g_W1c[base + 1808 + kk] = (int8_t)d2;   // class2 (0,2) -> w2
        g_W1c[base + 2208 + kk] = (int8_t)d0;   // class2 (2,0) -> w0
        g_W1c[base + 2688 + kk] = (int8_t)d2;   // class3 (1,2) -> w2
        g_W1c[base + 3088 + kk] = (int8_t)d1;   // class3 (2,1) -> w1
    }
}
__global__ void pad_w1c() {   // zero pad regions per (n, t): 384 bytes
    long idx = (long)blockIdx.x * blockDim.x + threadIdx.x;   // kH * 10 * 384
    if (idx >= (long)kH * kT * 384) return;
    int nt = (int)(idx / 384), r = (int)(idx % 384);
    int n = nt / kT, t = nt % kT;
    int j;
    if (r < 112)      j = 400 + r;
    else if (r < 208) j = 1312 + (r - 112);
    else if (r < 288) j = 2608 + (r - 208);
    else              j = 3488 + (r - 288);
    g_W1c[(long)n * kLd1 + (long)t * kL1Step + j] = 0;
}

__global__ void build_w2(const float* __restrict__ W) {   // [2048,2048] -> [2048, 6144]
    __shared__ float tile[32][33];
    int k0 = blockIdx.x * 32, n0 = blockIdx.y * 32;
    int tx = threadIdx.x & 31, ty = threadIdx.x >> 5;
    for (int i = 0; i < 32; i += 8)
        tile[ty + i][tx] = W[(long)(k0 + ty + i) * kH + n0 + tx];
    __syncthreads();
    float sc = g_sc[2];
    for (int i = 0; i < 32; i += 8) {
        int n = n0 + ty + i, k = k0 + tx;
        int d0, d1, d2;
        digits3(tile[tx][ty + i], sc, d0, d1, d2);
        long base = (long)n * kK2;
        g_W2c[base + k] = (int8_t)d0;
        g_W2c[base + kH + k] = (int8_t)d1;
        g_W2c[base + 2 * kH + k] = (int8_t)d2;
    }
}

__global__ void build_w3(const float* __restrict__ W) {   // [2048,1000] -> [1024, 6144]
    __shared__ float tile[32][33];
    int k0 = blockIdx.x * 32, n0 = blockIdx.y * 32;
    int tx = threadIdx.x & 31, ty = threadIdx.x >> 5;
    for (int i = 0; i < 32; i += 8) {
        int n = n0 + tx;
        tile[ty + i][tx] = (n < kO) ? W[(long)(k0 + ty + i) * kO + n] : 0.0f;
    }
    __syncthreads();
    float sc = g_sc[3];
    for (int i = 0; i < 32; i += 8) {
        int n = n0 + ty + i, k = k0 + tx;
        int d0, d1, d2;
        digits3(tile[tx][ty + i], sc, d0, d1, d2);
        long base = (long)n * kK2;
        g_W3c[base + k] = (int8_t)d0;
        g_W3c[base + kH + k] = (int8_t)d1;
        g_W3c[base + 2 * kH + k] = (int8_t)d2;
    }
}

// ---------------- main s8 HMMA GEMM + LIF kernel ----------------
// D[BM x 128] = A[m0:, bytes] @ Wc[n0:, bytes]^T, A k-byte wraps by amask.
// Chunks of 128 K-bytes; s32 accumulate within segments, fp32 fold at boundaries.
template <int BM>
__global__ __launch_bounds__(256) void snn_mma(
    const int8_t* __restrict__ A, long lda,
    const int8_t* __restrict__ Wc, long ldw,
    int NC, int amask, int4 se,
    const float* __restrict__ pdesc,
    const float* __restrict__ bias,
    float* __restrict__ vstate,
    float* __restrict__ acc,            // nullable (layer-1 running accumulator)
    int8_t* __restrict__ sout_c,        // nullable
    float* __restrict__ sout_f,         // nullable
    int N)
{
    constexpr int MI = BM / 32;
    constexpr uint32_t kABytes = BM * 128;
    constexpr uint32_t kStage = kABytes + 16384;

    extern __shared__ __align__(1024) char smem[];
    const uint32_t sbase = smem_u32(smem);
    const int tid = threadIdx.x, wid = tid >> 5, lid = tid & 31;
    const int m0 = blockIdx.y * BM, n0 = blockIdx.x * 128;
    const int wm = (wid >> 2) * (16 * MI);
    const int wn = (wid & 3) * 32;

    float accf[MI][4][4];
    int   acci[MI][4][4];
#pragma unroll
    for (int i = 0; i < MI; i++)
#pragma unroll
        for (int j = 0; j < 4; j++)
#pragma unroll
            for (int q = 0; q < 4; q++) { accf[i][j][q] = 0.0f; acci[i][j][q] = 0; }

    auto load_chunk = [&](int c, int b) {
        const int k0 = c * 128;
        const int ak = k0 & amask;
        const uint32_t abuf = sbase + (uint32_t)b * kStage;
        const uint32_t wbuf = abuf + kABytes;
#pragma unroll
        for (int p = 0; p < MI; p++) {
            int off = (p * 256 + tid) * 16;
            int row = off >> 7, colb = off & 127;
            cp16(abuf + sw128((uint32_t)off), A + (long)(m0 + row) * lda + ak + colb);
        }
#pragma unroll
        for (int p = 0; p < 4; p++) {
            int off = (p * 256 + tid) * 16;
            int row = off >> 7, colb = off & 127;
            cp16(wbuf + sw128((uint32_t)off), Wc + (long)(n0 + row) * ldw + k0 + colb);
        }
        cp_commit();
    };

    // per-lane ldmatrix address components (byte offsets; identical to fp16 layout)
    const int a_r = (lid & 7) + ((lid >> 3) & 1) * 8;
    const int a_k = (lid >> 4) * 16;
    const int b_r = (lid & 7) + (lid >> 4) * 8;
    const int b_k = ((lid >> 3) & 1) * 16;

    load_chunk(0, 0);
    load_chunk(1, 1);

    int sidx = 0, se_next = se.x;

    for (int c = 0; c < NC; c++) {
        const int b = c % 3;
        if (c + 1 < NC) cp_wait1(); else cp_wait0();
        __syncthreads();
        if (c + 2 < NC) load_chunk(c + 2, (c + 2) % 3);

        const uint32_t abuf = sbase + (uint32_t)b * kStage;
        const uint32_t wbuf = abuf + kABytes;

#pragma unroll
        for (int ks = 0; ks < 4; ks++) {
            uint32_t af[MI][4];
#pragma unroll
            for (int mi = 0; mi < MI; mi++) {
                uint32_t off = (uint32_t)((wm + mi * 16 + a_r) * 128 + ks * 32 + a_k);
                ldmx4(af[mi][0], af[mi][1], af[mi][2], af[mi][3], abuf + sw128(off));
            }
            uint32_t bfr[2][4];
#pragma unroll
            for (int np = 0; np < 2; np++) {
                uint32_t off = (uint32_t)((wn + np * 16 + b_r) * 128 + ks * 32 + b_k);
                ldmx4(bfr[np][0], bfr[np][1], bfr[np][2], bfr[np][3], wbuf + sw128(off));
            }
#pragma unroll
            for (int mi = 0; mi < MI; mi++)
#pragma unroll
                for (int ni = 0; ni < 4; ni++) {
                    const uint32_t* bp = &bfr[ni >> 1][(ni & 1) * 2];
                    mma_s8(acci[mi][ni][0], acci[mi][ni][1], acci[mi][ni][2], acci[mi][ni][3],
                           af[mi][0], af[mi][1], af[mi][2], af[mi][3], bp[0], bp[1]);
                }
        }

        // segment-boundary fold: s32 -> fp32 with weight 2^(-8*sidx)
        if (c + 1 == se_next) {
            float w = sidx == 0 ? 1.0f : sidx == 1 ? 0x1p-8f : sidx == 2 ? 0x1p-16f : 0x1p-24f;
#pragma unroll
            for (int mi = 0; mi < MI; mi++)
#pragma unroll
                for (int ni = 0; ni < 4; ni++)
#pragma unroll
                    for (int q = 0; q < 4; q++) {
                        accf[mi][ni][q] += __int2float_rn(acci[mi][ni][q]) * w;
                        acci[mi][ni][q] = 0;
                    }
            sidx++;
            se_next = sidx == 1 ? se.y : sidx == 2 ? se.z : sidx == 3 ? se.w : 0x7FFFFFFF;
        }
    }

    __syncthreads();

    // epilogue part 1: accumulators (descaled) -> smem fp32 [BM][128]
    const float dsc = *pdesc;
    {
        float* Ds = reinterpret_cast<float*>(smem);
        const int g = lid >> 2, tg = lid & 3;
#pragma unroll
        for (int mi = 0; mi < MI; mi++) {
#pragma unroll
            for (int ni = 0; ni < 4; ni++) {
                int row = wm + mi * 16 + g;
                int col = wn + ni * 8 + tg * 2;
                Ds[row * 128 + col]           = accf[mi][ni][0] * dsc;
                Ds[row * 128 + col + 1]       = accf[mi][ni][1] * dsc;
                Ds[(row + 8) * 128 + col]     = accf[mi][ni][2] * dsc;
                Ds[(row + 8) * 128 + col + 1] = accf[mi][ni][3] * dsc;
            }
        }
    }
    __syncthreads();

    // epilogue part 2: coalesced LIF RMW
    {
        float* Ds = reinterpret_cast<float*>(smem);
        int ncols = N - n0; if (ncols > 128) ncols = 128;
#pragma unroll 4
        for (int p = 0; p < BM / 8; p++) {
            int i4 = p * 256 + tid;
            int row = i4 >> 5, col = (i4 & 31) * 4;
            if (col < ncols) {
                long gidx = (long)(m0 + row) * N + n0 + col;
                float4 d = *reinterpret_cast<float4*>(&Ds[row * 128 + col]);
                if (acc) {
                    float4 a = *reinterpret_cast<const float4*>(&acc[gidx]);
                    d.x += a.x; d.y += a.y; d.z += a.z; d.w += a.w;
                    *reinterpret_cast<float4*>(&acc[gidx]) = d;
                }
                float4 bb = *reinterpret_cast<const float4*>(&bias[n0 + col]);
                float4 vo = *reinterpret_cast<float4*>(&vstate[gidx]);
                float cc, v, s[4];
                cc = d.x + bb.x; v = vo.x + (cc - vo.x) * 0.5f; s[0] = (v >= 1.0f) ? 1.0f : 0.0f; vo.x = v * (1.0f - s[0]);
                cc = d.y + bb.y; v = vo.y + (cc - vo.y) * 0.5f; s[1] = (v >= 1.0f) ? 1.0f : 0.0f; vo.y = v * (1.0f - s[1]);
                cc = d.z + bb.z; v = vo.z + (cc - vo.z) * 0.5f; s[2] = (v >= 1.0f) ? 1.0f : 0.0f; vo.z = v * (1.0f - s[2]);
                cc = d.w + bb.w; v = vo.w + (cc - vo.w) * 0.5f; s[3] = (v >= 1.0f) ? 1.0f : 0.0f; vo.w = v * (1.0f - s[3]);
                *reinterpret_cast<float4*>(&vstate[gidx]) = vo;
                if (sout_c) {
                    uchar4 so;
                    so.x = (unsigned char)(s[0] != 0.0f);
                    so.y = (unsigned char)(s[1] != 0.0f);
                    so.z = (unsigned char)(s[2] != 0.0f);
                    so.w = (unsigned char)(s[3] != 0.0f);
                    *reinterpret_cast<uchar4*>(&sout_c[gidx]) = so;
                }
                if (sout_f) {
                    float4 so; so.x = s[0]; so.y = s[1]; so.z = s[2]; so.w = s[3];
                    *reinterpret_cast<float4*>(&sout_f[gidx]) = so;
                }
            }
        }
    }
}

// ---------------- launch ----------------
extern "C" void kernel_launch(void* const* d_in, const int* in_sizes, int n_in,
                              void* d_out, int out_size) {
    const float* x  = (const float*)d_in[0];
    const float* W1 = (const float*)d_in[1];
    const float* b1 = (const float*)d_in[2];
    const float* W2 = (const float*)d_in[3];
    const float* b2 = (const float*)d_in[4];
    const float* W3 = (const float*)d_in[5];
    const float* b3 = (const float*)d_in[6];
    float* out = (float*)d_out;

    float *v1, *v2, *v3, *acc1, *desc;
    int8_t *s1, *s2, *a1c, *w1c, *w2c, *w3c;
    cudaGetSymbolAddress((void**)&v1, g_v1);
    cudaGetSymbolAddress((void**)&v2, g_v2);
    cudaGetSymbolAddress((void**)&v3, g_v3);
    cudaGetSymbolAddress((void**)&acc1, g_acc1);
    cudaGetSymbolAddress((void**)&s1, g_s1);
    cudaGetSymbolAddress((void**)&s2, g_s2);
    cudaGetSymbolAddress((void**)&a1c, g_A1c);
    cudaGetSymbolAddress((void**)&w1c, g_W1c);
    cudaGetSymbolAddress((void**)&w2c, g_W2c);
    cudaGetSymbolAddress((void**)&w3c, g_W3c);
    cudaGetSymbolAddress((void**)&desc, g_desc);

    constexpr unsigned kSmem128 = 3u * (128u * 128u + 16384u);   // 98304
    constexpr unsigned kSmem64  = 3u * (64u * 128u + 16384u);    // 73728
    cudaFuncSetAttribute(snn_mma<128>, cudaFuncAttributeMaxDynamicSharedMemorySize, kSmem128);
    cudaFuncSetAttribute(snn_mma<64>,  cudaFuncAttributeMaxDynamicSharedMemorySize, kSmem64);

    init_state<<<512, 256>>>();
    maxabs<<<256, 256>>>(x,  kB * kD, 0);
    maxabs<<<256, 256>>>(W1, kD * kH, 1);
    maxabs<<<256, 256>>>(W2, kH * kH, 2);
    maxabs<<<256, 256>>>(W3, kH * kO, 3);
    calc_scales<<<1, 32>>>();
    build_xcat<<<(int)(((long)kB * kLd1 + 255) / 256), 256>>>(x);
    build_w1<<<dim3(125, 64), 256>>>(W1);
    pad_w1c<<<(int)(((long)kH * kT * 384 + 255) / 256), 256>>>();
    build_w2<<<dim3(64, 64), 256>>>(W2);
    build_w3<<<dim3(64, 32), 256>>>(W3);

    dim3 blk(256);
    dim3 gridH(16, 8);    // N=2048 x M=1024, BM=128
    dim3 gridO(8, 16);    // N=1000 (8 tiles) x M=1024, BM=64

    const int4 se1 = make_int4(4, 11, 21, 28);
    const int4 se2 = make_int4(16, 32, 48, 1 << 30);

    for (int t = 0; t < kT; t++) {
        snn_mma<128><<<gridH, blk, kSmem128>>>(
            a1c + (long)t * kL1Step, kLd1, w1c + (long)t * kL1Step, kLd1,
            28, 0x7FFFFFFF, se1, desc + 0,
            b1, v1, acc1, s1, nullptr, kH);
        snn_mma<128><<<gridH, blk, kSmem128>>>(
            s1, kH, w2c, kK2,
            48, 2047, se2, desc + 1,
            b2, v2, nullptr, s2, nullptr, kH);
        snn_mma<64><<<gridO, blk, kSmem64>>>(
            s2, kH, w3c, kK2,
            48, 2047, se2, desc + 2,
            b3, v3, nullptr, nullptr, (t == kT - 1) ? out : nullptr, kO);
    }
}

// round 8
// speedup vs baseline: 3.9040x; 3.9040x over previous
#include <cuda_runtime.h>
#include <cuda_fp16.h>
#include <cstdint>

// SNNModel: 3-layer LIF SNN, T=10. B=1024, D=4000, H=2048, O=1000.
// HMMA (mma.sync m16n8k16, fp16 in / fp32 accum) with split-precision weights:
//   L2/L3: binary spikes exact in fp16; W = Wh+Wl fp16 2-split, K-concat K'=4096.
//   L1: x=xh+xl, W1=wh+wl; 3 cross terms (xh*wh, xh*wl, xl*wh), K'=1216/step.
// R8: all 10 layer-1 steps fused into ONE launch; v1 + prefix accumulator live in
// registers across steps; per-step LIF epilogue writes s1(t) straight from fragments.

namespace {
constexpr int kB = 1024, kD = 4000, kH = 2048, kO = 1000, kT = 10;
constexpr int kK1   = 1216;         // per-step K' for layer 1 (3*400 + 16 pad), 19 chunks
constexpr int kLd1  = kT * kK1;     // 12160
constexpr int kNC1  = kLd1 / 64;    // 190 chunks
constexpr int kK2   = 2 * kH;       // 4096
constexpr int kOp   = 1024;
}

// ---------------- persistent device buffers ----------------
__device__ __align__(16) float g_v2[kB * kH];
__device__ __align__(16) float g_v3[kB * kO];
__device__ __align__(16) __half g_s1all[(size_t)kT * kB * kH];   // per-step layer-1 spikes
__device__ __align__(16) __half g_s2[kB * kH];
__device__ __align__(16) __half g_A1c[(size_t)kB * kLd1];   // [B, 10*1216]
__device__ __align__(16) __half g_W1c[(size_t)kH * kLd1];   // [H, 10*1216] (N-major, K contig)
__device__ __align__(16) __half g_W2c[(size_t)kH * kK2];    // [H, 4096]
__device__ __align__(16) __half g_W3c[(size_t)kOp * kK2];   // [1024, 4096]

// ---------------- PTX helpers ----------------
__device__ __forceinline__ uint32_t smem_u32(const void* p) {
    uint32_t a;
    asm("{ .reg .u64 t; cvta.to.shared.u64 t, %1; cvt.u32.u64 %0, t; }" : "=r"(a) : "l"(p));
    return a;
}
__device__ __forceinline__ void cp16(uint32_t dst, const void* src) {
    asm volatile("cp.async.cg.shared.global [%0], [%1], 16;" :: "r"(dst), "l"(src));
}
__device__ __forceinline__ void cp_commit() { asm volatile("cp.async.commit_group;" ::: "memory"); }
__device__ __forceinline__ void cp_wait1()  { asm volatile("cp.async.wait_group 1;" ::: "memory"); }
__device__ __forceinline__ void cp_wait0()  { asm volatile("cp.async.wait_group 0;" ::: "memory"); }
__device__ __forceinline__ void ldmx4(uint32_t& r0, uint32_t& r1, uint32_t& r2, uint32_t& r3,
                                      uint32_t addr) {
    asm volatile("ldmatrix.sync.aligned.m8n8.x4.shared.b16 {%0,%1,%2,%3}, [%4];"
                 : "=r"(r0), "=r"(r1), "=r"(r2), "=r"(r3) : "r"(addr));
}
__device__ __forceinline__ void mma16816(float& c0, float& c1, float& c2, float& c3,
                                         uint32_t a0, uint32_t a1, uint32_t a2, uint32_t a3,
                                         uint32_t b0, uint32_t b1) {
    asm volatile(
        "mma.sync.aligned.m16n8k16.row.col.f32.f16.f16.f32 "
        "{%0,%1,%2,%3}, {%4,%5,%6,%7}, {%8,%9}, {%0,%1,%2,%3};"
        : "+f"(c0), "+f"(c1), "+f"(c2), "+f"(c3)
        : "r"(a0), "r"(a1), "r"(a2), "r"(a3), "r"(b0), "r"(b1));
}
__device__ __forceinline__ uint32_t sw128(uint32_t off) {
    return off ^ ((off >> 3) & 0x70);
}

// ---------------- init / precompute kernels ----------------
__global__ void init_state() {
    int stride = gridDim.x * blockDim.x;
    int i0 = blockIdx.x * blockDim.x + threadIdx.x;
    for (int i = i0; i < kB * kH; i += stride) g_v2[i] = 0.0f;
    for (int i = i0; i < kB * kO; i += stride) g_v3[i] = 0.0f;
}

// A1c[m, t*1216 + j] : [xh(400) | xh(400) | xl(400) | pad16]
__global__ void build_xcat(const float* __restrict__ x) {
    long idx = (long)blockIdx.x * blockDim.x + threadIdx.x;
    if (idx >= (long)kB * kLd1) return;
    int m = (int)(idx / kLd1), c = (int)(idx % kLd1);
    int t = c / kK1, j = c % kK1;
    __half o = __float2half_rn(0.0f);
    if (j < 1200) {
        int seg = j / 400, kk = j % 400;
        float xv = x[(long)m * kD + t * 400 + kk];
        __half h = __float2half_rn(xv);
        o = (seg < 2) ? h : __float2half_rn(xv - __half2float(h));
    }
    g_A1c[idx] = o;
}

// W1c per step block: [wh(400) | wl(400) | wh(400) | pad16]. Pairs: xh*wh, xh*wl, xl*wh.
__global__ void build_w1(const float* __restrict__ W) {   // W: [4000, 2048]
    __shared__ float tile[32][33];
    int k0 = blockIdx.x * 32, n0 = blockIdx.y * 32;
    int tx = threadIdx.x & 31, ty = threadIdx.x >> 5;
    for (int i = 0; i < 32; i += 8)
        tile[ty + i][tx] = W[(long)(k0 + ty + i) * kH + n0 + tx];
    __syncthreads();
    for (int i = 0; i < 32; i += 8) {
        int n = n0 + ty + i, kg = k0 + tx;
        int t = kg / 400, kk = kg % 400;
        float v = tile[tx][ty + i];
        __half h = __float2half_rn(v);
        __half l = __float2half_rn(v - __half2float(h));
        long base = (long)n * kLd1 + (long)t * kK1;
        g_W1c[base + kk]       = h;
        g_W1c[base + 400 + kk] = l;
        g_W1c[base + 800 + kk] = h;
    }
}
__global__ void pad_w1() {   // zero cols [1200,1216) of every step block
    long idx = (long)blockIdx.x * blockDim.x + threadIdx.x;   // kH * 10 * 16
    if (idx >= (long)kH * kT * 16) return;
    int n = (int)(idx / (kT * 16)), r = (int)(idx % (kT * 16));
    int t = r / 16, j = 1200 + r % 16;
    g_W1c[(long)n * kLd1 + (long)t * kK1 + j] = __float2half_rn(0.0f);
}

__global__ void build_w2(const float* __restrict__ W) {   // [2048,2048] -> [2048, 4096]
    __shared__ float tile[32][33];
    int k0 = blockIdx.x * 32, n0 = blockIdx.y * 32;
    int tx = threadIdx.x & 31, ty = threadIdx.x >> 5;
    for (int i = 0; i < 32; i += 8)
        tile[ty + i][tx] = W[(long)(k0 + ty + i) * kH + n0 + tx];
    __syncthreads();
    for (int i = 0; i < 32; i += 8) {
        int n = n0 + ty + i, k = k0 + tx;
        float v = tile[tx][ty + i];
        __half h = __float2half_rn(v);
        __half l = __float2half_rn(v - __half2float(h));
        long base = (long)n * kK2;
        g_W2c[base + k] = h; g_W2c[base + kH + k] = l;
    }
}

__global__ void build_w3(const float* __restrict__ W) {   // [2048,1000] -> [1024, 4096]
    __shared__ float tile[32][33];
    int k0 = blockIdx.x * 32, n0 = blockIdx.y * 32;
    int tx = threadIdx.x & 31, ty = threadIdx.x >> 5;
    for (int i = 0; i < 32; i += 8) {
        int n = n0 + tx;
        tile[ty + i][tx] = (n < kO) ? W[(long)(k0 + ty + i) * kO + n] : 0.0f;
    }
    __syncthreads();
    for (int i = 0; i < 32; i += 8) {
        int n = n0 + ty + i, k = k0 + tx;
        float v = tile[tx][ty + i];
        __half h = __float2half_rn(v);
        __half l = __float2half_rn(v - __half2float(h));
        long base = (long)n * kK2;
        g_W3c[base + k] = h; g_W3c[base + kH + k] = l;
    }
}

// ---------------- layer-1 mega kernel: all T steps in one launch ----------------
// 128x128 output tile; K processed serially over all steps. accf is the running
// prefix sum (never reset); v1 lives in registers; per-step LIF at 19-chunk
// boundaries writes s1(t) directly from the fragment layout.
__global__ __launch_bounds__(256) void snn_l1(
    const __half* __restrict__ A,      // g_A1c
    const __half* __restrict__ Wc,     // g_W1c
    const float* __restrict__ bias,
    __half* __restrict__ s1all)        // [T, B*H]
{
    constexpr uint32_t kABytes = 128 * 128;          // 16384
    constexpr uint32_t kStage = kABytes + 16384;     // 32768

    extern __shared__ __align__(1024) char smem[];
    const uint32_t sbase = smem_u32(smem);
    const int tid = threadIdx.x, wid = tid >> 5, lid = tid & 31;
    const int m0 = blockIdx.y * 128, n0 = blockIdx.x * 128;
    const int wm = (wid >> 2) * 64;
    const int wn = (wid & 3) * 32;
    const int g = lid >> 2, tg = lid & 3;

    float accf[4][4][4];   // running prefix accumulator (never reset)
    float v1[4][4][4];     // membrane potential
#pragma unroll
    for (int i = 0; i < 4; i++)
#pragma unroll
        for (int j = 0; j < 4; j++)
#pragma unroll
            for (int q = 0; q < 4; q++) { accf[i][j][q] = 0.0f; v1[i][j][q] = 0.0f; }

    // per-thread bias values (col depends only on ni, tg)
    float bv[4][2];
#pragma unroll
    for (int ni = 0; ni < 4; ni++) {
        int col = n0 + wn + ni * 8 + tg * 2;
        bv[ni][0] = bias[col];
        bv[ni][1] = bias[col + 1];
    }

    auto load_chunk = [&](int c, int b) {
        const int k0 = c * 64;
        const uint32_t abuf = sbase + (uint32_t)b * kStage;
        const uint32_t wbuf = abuf + kABytes;
#pragma unroll
        for (int p = 0; p < 4; p++) {
            int off = (p * 256 + tid) * 16;
            int row = off >> 7, colb = off & 127;
            cp16(abuf + sw128((uint32_t)off), A + (long)(m0 + row) * kLd1 + k0 + (colb >> 1));
        }
#pragma unroll
        for (int p = 0; p < 4; p++) {
            int off = (p * 256 + tid) * 16;
            int row = off >> 7, colb = off & 127;
            cp16(wbuf + sw128((uint32_t)off), Wc + (long)(n0 + row) * kLd1 + k0 + (colb >> 1));
        }
        cp_commit();
    };

    const int a_r = (lid & 7) + ((lid >> 3) & 1) * 8;
    const int a_k = (lid >> 4) * 16;
    const int b_r = (lid & 7) + (lid >> 4) * 8;
    const int b_k = ((lid >> 3) & 1) * 16;

    load_chunk(0, 0);
    load_chunk(1, 1);

    for (int c = 0; c < kNC1; c++) {
        const int b = c % 3;
        if (c + 1 < kNC1) cp_wait1(); else cp_wait0();
        __syncthreads();
        if (c + 2 < kNC1) load_chunk(c + 2, (c + 2) % 3);

        const uint32_t abuf = sbase + (uint32_t)b * kStage;
        const uint32_t wbuf = abuf + kABytes;
#pragma unroll
        for (int ks = 0; ks < 4; ks++) {
            uint32_t af[4][4];
#pragma unroll
            for (int mi = 0; mi < 4; mi++) {
                uint32_t off = (uint32_t)((wm + mi * 16 + a_r) * 128 + ks * 32 + a_k);
                ldmx4(af[mi][0], af[mi][1], af[mi][2], af[mi][3], abuf + sw128(off));
            }
            uint32_t bfr[2][4];
#pragma unroll
            for (int np = 0; np < 2; np++) {
                uint32_t off = (uint32_t)((wn + np * 16 + b_r) * 128 + ks * 32 + b_k);
                ldmx4(bfr[np][0], bfr[np][1], bfr[np][2], bfr[np][3], wbuf + sw128(off));
            }
#pragma unroll
            for (int mi = 0; mi < 4; mi++)
#pragma unroll
                for (int ni = 0; ni < 4; ni++) {
                    const uint32_t* bp = &bfr[ni >> 1][(ni & 1) * 2];
                    mma16816(accf[mi][ni][0], accf[mi][ni][1], accf[mi][ni][2], accf[mi][ni][3],
                             af[mi][0], af[mi][1], af[mi][2], af[mi][3], bp[0], bp[1]);
                }
        }

        // step boundary: LIF in registers, spikes straight to gmem
        if (c % 19 == 18) {
            const int st = c / 19;
            __half* sout = s1all + (size_t)st * kB * kH;
#pragma unroll
            for (int mi = 0; mi < 4; mi++) {
                int row0 = m0 + wm + mi * 16 + g;
#pragma unroll
                for (int ni = 0; ni < 4; ni++) {
                    int col = n0 + wn + ni * 8 + tg * 2;
                    float s[4];
#pragma unroll
                    for (int q = 0; q < 4; q++) {
                        float cc = accf[mi][ni][q] + bv[ni][q & 1];
                        float v = v1[mi][ni][q];
                        v = v + (cc - v) * 0.5f;
                        s[q] = (v >= 1.0f) ? 1.0f : 0.0f;
                        v1[mi][ni][q] = v * (1.0f - s[q]);
                    }
                    *reinterpret_cast<__half2*>(&sout[(long)row0 * kH + col]) =
                        __floats2half2_rn(s[0], s[1]);
                    *reinterpret_cast<__half2*>(&sout[(long)(row0 + 8) * kH + col]) =
                        __floats2half2_rn(s[2], s[3]);
                }
            }
        }
    }
}

// ---------------- L2/L3 HMMA GEMM + LIF kernel (R5 form) ----------------
// D[BM x 128] tile = A[m0:,:K'] @ Wc[n0:,:K']^T, A k-index wraps mod 2048.
template <int BM>
__global__ __launch_bounds__(256) void snn_mma(
    const __half* __restrict__ A, long lda,
    const __half* __restrict__ Wc, long ldw,
    int Kp,
    const float* __restrict__ bias,
    float* __restrict__ vstate,
    __half* __restrict__ sout_h,        // nullable
    float* __restrict__ sout_f,         // nullable
    int N)
{
    constexpr int MI = BM / 32;
    constexpr uint32_t kABytes = BM * 128;
    constexpr uint32_t kStage = kABytes + 16384;

    extern __shared__ __align__(1024) char smem[];
    const uint32_t sbase = smem_u32(smem);
    const int tid = threadIdx.x, wid = tid >> 5, lid = tid & 31;
    const int m0 = blockIdx.y * BM, n0 = blockIdx.x * 128;
    const int wm = (wid >> 2) * (16 * MI);
    const int wn = (wid & 3) * 32;

    const int NC = Kp / 64;

    float accf[MI][4][4];
#pragma unroll
    for (int i = 0; i < MI; i++)
#pragma unroll
        for (int j = 0; j < 4; j++)
#pragma unroll
            for (int q = 0; q < 4; q++) accf[i][j][q] = 0.0f;

    auto load_chunk = [&](int c, int b) {
        const int k0 = c * 64;
        const int ak = k0 & 2047;               // A wraps mod 2048 (K-concat reuse)
        const uint32_t abuf = sbase + (uint32_t)b * kStage;
        const uint32_t wbuf = abuf + kABytes;
#pragma unroll
        for (int p = 0; p < MI; p++) {
            int off = (p * 256 + tid) * 16;
            int row = off >> 7, colb = off & 127;
            cp16(abuf + sw128((uint32_t)off), A + (long)(m0 + row) * lda + ak + (colb >> 1));
        }
#pragma unroll
        for (int p = 0; p < 4; p++) {
            int off = (p * 256 + tid) * 16;
            int row = off >> 7, colb = off & 127;
            cp16(wbuf + sw128((uint32_t)off), Wc + (long)(n0 + row) * ldw + k0 + (colb >> 1));
        }
        cp_commit();
    };

    const int a_r = (lid & 7) + ((lid >> 3) & 1) * 8;
    const int a_k = (lid >> 4) * 16;
    const int b_r = (lid & 7) + (lid >> 4) * 8;
    const int b_k = ((lid >> 3) & 1) * 16;

    load_chunk(0, 0);
    load_chunk(1, 1);

    for (int c = 0; c < NC; c++) {
        const int b = c % 3;
        if (c + 1 < NC) cp_wait1(); else cp_wait0();
        __syncthreads();
        if (c + 2 < NC) load_chunk(c + 2, (c + 2) % 3);

        const uint32_t abuf = sbase + (uint32_t)b * kStage;
        const uint32_t wbuf = abuf + kABytes;
#pragma unroll
        for (int ks = 0; ks < 4; ks++) {
            uint32_t af[MI][4];
#pragma unroll
            for (int mi = 0; mi < MI; mi++) {
                uint32_t off = (uint32_t)((wm + mi * 16 + a_r) * 128 + ks * 32 + a_k);
                ldmx4(af[mi][0], af[mi][1], af[mi][2], af[mi][3], abuf + sw128(off));
            }
            uint32_t bfr[2][4];
#pragma unroll
            for (int np = 0; np < 2; np++) {
                uint32_t off = (uint32_t)((wn + np * 16 + b_r) * 128 + ks * 32 + b_k);
                ldmx4(bfr[np][0], bfr[np][1], bfr[np][2], bfr[np][3], wbuf + sw128(off));
            }
#pragma unroll
            for (int mi = 0; mi < MI; mi++)
#pragma unroll
                for (int ni = 0; ni < 4; ni++) {
                    const uint32_t* bp = &bfr[ni >> 1][(ni & 1) * 2];
                    mma16816(accf[mi][ni][0], accf[mi][ni][1], accf[mi][ni][2], accf[mi][ni][3],
                             af[mi][0], af[mi][1], af[mi][2], af[mi][3], bp[0], bp[1]);
                }
        }
    }

    __syncthreads();

    // epilogue part 1: accumulators -> smem fp32 [BM][128]
    {
        float* Ds = reinterpret_cast<float*>(smem);
        const int g = lid >> 2, tg = lid & 3;
#pragma unroll
        for (int mi = 0; mi < MI; mi++) {
#pragma unroll
            for (int ni = 0; ni < 4; ni++) {
                int row = wm + mi * 16 + g;
                int col = wn + ni * 8 + tg * 2;
                Ds[row * 128 + col]           = accf[mi][ni][0];
                Ds[row * 128 + col + 1]       = accf[mi][ni][1];
                Ds[(row + 8) * 128 + col]     = accf[mi][ni][2];
                Ds[(row + 8) * 128 + col + 1] = accf[mi][ni][3];
            }
        }
    }
    __syncthreads();

    // epilogue part 2: coalesced LIF RMW
    {
        float* Ds = reinterpret_cast<float*>(smem);
        int ncols = N - n0; if (ncols > 128) ncols = 128;
#pragma unroll 4
        for (int p = 0; p < BM / 8; p++) {
            int i4 = p * 256 + tid;
            int row = i4 >> 5, col = (i4 & 31) * 4;
            if (col < ncols) {
                long gidx = (long)(m0 + row) * N + n0 + col;
                float4 d = *reinterpret_cast<float4*>(&Ds[row * 128 + col]);
                float4 bb = *reinterpret_cast<const float4*>(&bias[n0 + col]);
                float4 vo = *reinterpret_cast<float4*>(&vstate[gidx]);
                float cc, v, s[4];
                cc = d.x + bb.x; v = vo.x + (cc - vo.x) * 0.5f; s[0] = (v >= 1.0f) ? 1.0f : 0.0f; vo.x = v * (1.0f - s[0]);
                cc = d.y + bb.y; v = vo.y + (cc - vo.y) * 0.5f; s[1] = (v >= 1.0f) ? 1.0f : 0.0f; vo.y = v * (1.0f - s[1]);
                cc = d.z + bb.z; v = vo.z + (cc - vo.z) * 0.5f; s[2] = (v >= 1.0f) ? 1.0f : 0.0f; vo.z = v * (1.0f - s[2]);
                cc = d.w + bb.w; v = vo.w + (cc - vo.w) * 0.5f; s[3] = (v >= 1.0f) ? 1.0f : 0.0f; vo.w = v * (1.0f - s[3]);
                *reinterpret_cast<float4*>(&vstate[gidx]) = vo;
                if (sout_h) {
                    __half2 h0 = __floats2half2_rn(s[0], s[1]);
                    __half2 h1 = __floats2half2_rn(s[2], s[3]);
                    *reinterpret_cast<__half2*>(&sout_h[gidx]) = h0;
                    *reinterpret_cast<__half2*>(&sout_h[gidx + 2]) = h1;
                }
                if (sout_f) {
                    float4 so; so.x = s[0]; so.y = s[1]; so.z = s[2]; so.w = s[3];
                    *reinterpret_cast<float4*>(&sout_f[gidx]) = so;
                }
            }
        }
    }
}

// ---------------- launch ----------------
extern "C" void kernel_launch(void* const* d_in, const int* in_sizes, int n_in,
                              void* d_out, int out_size) {
    const float* x  = (const float*)d_in[0];
    const float* W1 = (const float*)d_in[1];
    const float* b1 = (const float*)d_in[2];
    const float* W2 = (const float*)d_in[3];
    const float* b2 = (const float*)d_in[4];
    const float* W3 = (const float*)d_in[5];
    const float* b3 = (const float*)d_in[6];
    float* out = (float*)d_out;

    float *v2, *v3;
    __half *s1all, *s2, *a1c, *w1c, *w2c, *w3c;
    cudaGetSymbolAddress((void**)&v2, g_v2);
    cudaGetSymbolAddress((void**)&v3, g_v3);
    cudaGetSymbolAddress((void**)&s1all, g_s1all);
    cudaGetSymbolAddress((void**)&s2, g_s2);
    cudaGetSymbolAddress((void**)&a1c, g_A1c);
    cudaGetSymbolAddress((void**)&w1c, g_W1c);
    cudaGetSymbolAddress((void**)&w2c, g_W2c);
    cudaGetSymbolAddress((void**)&w3c, g_W3c);

    constexpr unsigned kSmem128 = 3u * (128u * 128u + 16384u);   // 98304
    constexpr unsigned kSmem64  = 3u * (64u * 128u + 16384u);    // 73728
    cudaFuncSetAttribute(snn_l1,       cudaFuncAttributeMaxDynamicSharedMemorySize, kSmem128);
    cudaFuncSetAttribute(snn_mma<128>, cudaFuncAttributeMaxDynamicSharedMemorySize, kSmem128);
    cudaFuncSetAttribute(snn_mma<64>,  cudaFuncAttributeMaxDynamicSharedMemorySize, kSmem64);

    init_state<<<512, 256>>>();
    build_xcat<<<(int)(((long)kB * kLd1 + 255) / 256), 256>>>(x);
    build_w1<<<dim3(125, 64), 256>>>(W1);
    pad_w1<<<(int)(((long)kH * kT * 16 + 255) / 256), 256>>>();
    build_w2<<<dim3(64, 64), 256>>>(W2);
    build_w3<<<dim3(64, 32), 256>>>(W3);

    dim3 blk(256);
    dim3 gridH(16, 8);    // N=2048 x M=1024, BM=128
    dim3 gridO(8, 16);    // N=1000 (8 tiles of 128) x M=1024, BM=64

    // all 10 layer-1 steps in one launch
    snn_l1<<<gridH, blk, kSmem128>>>(a1c, w1c, b1, s1all);

    for (int t = 0; t < kT; t++) {
        snn_mma<128><<<gridH, blk, kSmem128>>>(
            s1all + (size_t)t * kB * kH, kH, w2c, kK2, kK2,
            b2, v2, s2, nullptr, kH);
        snn_mma<64><<<gridO, blk, kSmem64>>>(
            s2, kH, w3c, kK2, kK2,
            b3, v3, nullptr, (t == kT - 1) ? out : nullptr, kO);
    }
}